// round 16
// baseline (speedup 1.0000x reference)
#include <cuda_runtime.h>
#include <cuda_bf16.h>
#include <cstdint>

// B=32, P=64, D=34, L=1048576
// inputs: preds [B, L] f32, gts [B, P, D, 3] f32   output: [B] f32
// out[b] = sum_{valid} |preds[b, idx] - val| / #persons-with-any-valid-dim
//
// Single kernel, 32 CTAs x 1024 threads, minimal critical path; gathers are
// PREDICATED on the valid flag (flag arrives with idx -> no extra chain depth,
// ~30% fewer gather lines issued).

#define RB   32
#define RP   64
#define RD   34
#define RL   1048576
#define NPD  (RP * RD)            // 2176 entries per batch
#define NTHREADS 1024
#define NWARPS  (NTHREADS / 32)   // 32
#define EPW  68                   // entries per warp (= 2 whole persons)

__global__ __launch_bounds__(NTHREADS, 1)
void regl1_kernel(const float* __restrict__ preds,
                  const float* __restrict__ gts,
                  float* __restrict__ out)
{
    const int b    = blockIdx.x;
    const int tid  = threadIdx.x;
    const int warp = tid >> 5;
    const int lane = tid & 31;

    __shared__ float2 s_part[NWARPS];      // {sum, np} per warp

    const float* __restrict__ g  = gts + (size_t)b * NPD * 3 + (size_t)warp * EPW * 3;
    const float* __restrict__ pr = preds + (size_t)b * RL;

    // lane handles e0 = lane, e1 = lane+32, e2 = lane+64 (lane < 4)
    const bool has2 = (lane < EPW - 64);
    const int  o0 = 3 * lane;
    const int  o1 = 3 * (lane + 32);
    const int  o2 = has2 ? 3 * (lane + 64) : 0;    // in-bounds dummy

    // batch all independent gts loads (idx+flg together: predicate is free)
    const unsigned i0 = (unsigned)(int)g[o0 + 1];
    const unsigned i1 = (unsigned)(int)g[o1 + 1];
    const unsigned i2 = (unsigned)(int)g[o2 + 1];
    const float flg0 = g[o0 + 2];
    const float flg1 = g[o1 + 2];
    const float flg2 = has2 ? g[o2 + 2] : -1.0f;
    const float val0 = g[o0 + 0];
    const float val1 = g[o1 + 0];
    const float val2 = g[o2 + 0];

    const bool v0 = (flg0 > 0.0f);
    const bool v1 = (flg1 > 0.0f);
    const bool v2 = (flg2 > 0.0f);

    // predicated gathers: invalid lanes issue NO memory request
    float gat0 = 0.0f, gat1 = 0.0f, gat2 = 0.0f;
    if (v0) gat0 = __ldg(pr + i0);         // idx in [0,L) by setup
    if (v1) gat1 = __ldg(pr + i1);
    if (v2) gat2 = __ldg(pr + i2);

    float sum = 0.0f;
    if (v0) sum += fabsf(gat0 - val0);
    if (v1) sum += fabsf(gat1 - val1);
    if (v2) sum += fabsf(gat2 - val2);

    // person A = segment entries 0..33  (e0 all lanes; e1 lanes 0,1)
    // person B = segment entries 34..67 (e1 lanes 2..31; e2 lanes 0..3)
    const unsigned b0 = __ballot_sync(0xFFFFFFFFu, v0);
    const unsigned b1 = __ballot_sync(0xFFFFFFFFu, v1);
    const unsigned b2 = __ballot_sync(0xFFFFFFFFu, v2);
    const float np = (float)(((b0 | (b1 & 0x3u)) != 0u) +
                             (((b1 & ~0x3u) | b2) != 0u));

    #pragma unroll
    for (int off = 16; off > 0; off >>= 1)
        sum += __shfl_down_sync(0xFFFFFFFFu, sum, off);
    if (lane == 0) s_part[warp] = make_float2(sum, np);
    __syncthreads();

    if (warp == 0) {
        float2 v = s_part[lane];               // 32 warps
        #pragma unroll
        for (int off = 16; off > 0; off >>= 1) {
            v.x += __shfl_down_sync(0xFFFFFFFFu, v.x, off);
            v.y += __shfl_down_sync(0xFFFFFFFFu, v.y, off);
        }
        if (lane == 0)
            out[b] = v.x / v.y;                // reference guarantees np >= 1
    }
}

extern "C" void kernel_launch(void* const* d_in, const int* in_sizes, int n_in,
                              void* d_out, int out_size)
{
    const float* preds = (const float*)d_in[0];
    const float* gts   = (const float*)d_in[1];
    float* out         = (float*)d_out;
    regl1_kernel<<<RB, NTHREADS>>>(preds, gts, out);
}